// round 6
// baseline (speedup 1.0000x reference)
#include <cuda_runtime.h>
#include <math.h>

#define HKD  128
#define NKH  16
#define NVH  32
#define QKVD 8192
#define BMAX 256

// scratch (written by prep, read by stream; both launched every call)
__device__ __align__(16) float g_qk[BMAX * NKH * 256];    // per pair: qn[128], kn[128]
__device__ __align__(16) float g_v [BMAX * NVH * HKD];    // per bh: v[128]
__device__ __align__(16) float g_sc[BMAX * NVH * 4];      // per bh: eg, beta, kq

__device__ __forceinline__ float wredu(float v) {
#pragma unroll
    for (int o = 16; o; o >>= 1) v += __shfl_xor_sync(0xffffffffu, v, o);
    return v;
}

__device__ __forceinline__ float dot4(float4 a, float4 b) {
    return a.x * b.x + a.y * b.y + a.z * b.z + a.w * b.w;
}

// ---------------- kernel 1: conv + norms + gates, once per (b, k-head) ----
__global__ __launch_bounds__(128) void gdn_prep_kernel(
    const float* __restrict__ mixed_qkv,
    const float* __restrict__ bgate,
    const float* __restrict__ agate,
    const float* __restrict__ conv_state,
    const float* __restrict__ conv_w,
    const float* __restrict__ alog,
    const float* __restrict__ dt_bias)
{
    const int pair = blockIdx.x;
    const int b    = pair >> 4;
    const int hp   = pair & 15;
    const int t    = threadIdx.x;
    const int lane = t & 31;
    const int wid  = t >> 5;

    __shared__ float red[12];

    const float* cs = conv_state + (size_t)b * 3 * QKVD;
    const float* mq = mixed_qkv  + (size_t)b * QKVD;

    const int cq  = hp * HKD + t;
    const int ck  = NKH * HKD + hp * HKD + t;
    const int cv0 = 2 * NKH * HKD + hp * 2 * HKD + t;
    const int cv1 = cv0 + HKD;

    float4 w = *(const float4*)(conv_w + (size_t)cq * 4);
    float x  = cs[cq] * w.x + cs[QKVD + cq] * w.y + cs[2 * QKVD + cq] * w.z + mq[cq] * w.w;
    const float qx = x / (1.f + expf(-x));

    w = *(const float4*)(conv_w + (size_t)ck * 4);
    x = cs[ck] * w.x + cs[QKVD + ck] * w.y + cs[2 * QKVD + ck] * w.z + mq[ck] * w.w;
    const float kx = x / (1.f + expf(-x));

    w = *(const float4*)(conv_w + (size_t)cv0 * 4);
    x = cs[cv0] * w.x + cs[QKVD + cv0] * w.y + cs[2 * QKVD + cv0] * w.z + mq[cv0] * w.w;
    const float v0 = x / (1.f + expf(-x));

    w = *(const float4*)(conv_w + (size_t)cv1 * 4);
    x = cs[cv1] * w.x + cs[QKVD + cv1] * w.y + cs[2 * QKVD + cv1] * w.z + mq[cv1] * w.w;
    const float v1 = x / (1.f + expf(-x));

    float pq = wredu(qx * qx);
    float pk = wredu(kx * kx);
    float pc = wredu(qx * kx);
    if (lane == 0) { red[wid] = pq; red[4 + wid] = pk; red[8 + wid] = pc; }
    __syncthreads();

    const float rq = rsqrtf(red[0] + red[1] + red[2] + red[3] + 1e-6f)
                     * 0.08838834764831845f;                        // * HK^-0.5
    const float rk = rsqrtf(red[4] + red[5] + red[6] + red[7] + 1e-6f);
    const float kq = (red[8] + red[9] + red[10] + red[11]) * rq * rk;

    g_qk[(size_t)pair * 256 + t]       = qx * rq;
    g_qk[(size_t)pair * 256 + 128 + t] = kx * rk;

    const int bh0 = b * NVH + hp * 2;
    g_v[(size_t)bh0 * HKD + t]         = v0;
    g_v[(size_t)(bh0 + 1) * HKD + t]   = v1;

    if (t < 2) {
        const int h  = hp * 2 + t;
        const int bh = b * NVH + h;
        const float aa   = agate[(size_t)b * NVH + h] + dt_bias[h];
        const float sp   = fmaxf(aa, 0.f) + log1pf(expf(-fabsf(aa)));
        const float eg   = expf(-expf(alog[h]) * sp);
        const float beta = 1.f / (1.f + expf(-bgate[(size_t)b * NVH + h]));
        g_sc[bh * 4 + 0] = eg;
        g_sc[bh * 4 + 1] = beta;
        g_sc[bh * 4 + 2] = kq;
    }
}

// ---------------- kernel 2: pure state streamer, no barriers ---------------
__global__ __launch_bounds__(128) void gdn_stream_kernel(
    const float* __restrict__ ssm,
    float* __restrict__ out)
{
    const int bh   = blockIdx.x;
    const int pair = (bh >> 5) * NKH + ((bh & 31) >> 1);
    const int t    = threadIdx.x;
    const int lane = t & 31;
    const int wid  = t >> 5;

    __shared__ __align__(16) float v_s[HKD];

    // prefetch batch 0 first — loads start at instruction 0
    const float4* Sb = (const float4*)(ssm + (size_t)bh * HKD * HKD)
                       + (size_t)wid * 32 * 32 + lane;
    float4 c0 = __ldcs(Sb + 0 * 32);
    float4 c1 = __ldcs(Sb + 1 * 32);
    float4 c2 = __ldcs(Sb + 2 * 32);
    float4 c3 = __ldcs(Sb + 3 * 32);

    // L2-hot prep loads (kernel 1 just wrote these)
    const float4 q4 = ((const float4*)(g_qk + (size_t)pair * 256))[lane];
    const float4 k4 = ((const float4*)(g_qk + (size_t)pair * 256 + 128))[lane];
    v_s[t] = g_v[(size_t)bh * HKD + t];
    const float eg   = g_sc[bh * 4 + 0];
    const float beta = g_sc[bh * 4 + 1];
    const float kq   = g_sc[bh * 4 + 2];
    __syncwarp();   // v_s visibility within the warp (only sync in the kernel)

    float*       op = out + (size_t)bh * HKD + wid * 32;
    const float* vr = v_s + wid * 32;

#pragma unroll
    for (int j = 0; j < 8; j++) {
        float4 n0 = {}, n1 = {}, n2 = {}, n3 = {};
        if (j < 7) {
            n0 = __ldcs(Sb + ((j + 1) * 4 + 0) * 32);
            n1 = __ldcs(Sb + ((j + 1) * 4 + 1) * 32);
            n2 = __ldcs(Sb + ((j + 1) * 4 + 2) * 32);
            n3 = __ldcs(Sb + ((j + 1) * 4 + 3) * 32);
        }

        float dk0 = dot4(c0, k4), dq0 = dot4(c0, q4);
        float dk1 = dot4(c1, k4), dq1 = dot4(c1, q4);
        float dk2 = dot4(c2, k4), dq2 = dot4(c2, q4);
        float dk3 = dot4(c3, k4), dq3 = dot4(c3, q4);

        dk0 = wredu(dk0); dq0 = wredu(dq0);
        dk1 = wredu(dk1); dq1 = wredu(dq1);
        dk2 = wredu(dk2); dq2 = wredu(dq2);
        dk3 = wredu(dk3); dq3 = wredu(dq3);

        if (lane == 0) {
            const int r = j * 4;
            op[r + 0] = eg * dq0 + beta * (vr[r + 0] - eg * dk0) * kq;
            op[r + 1] = eg * dq1 + beta * (vr[r + 1] - eg * dk1) * kq;
            op[r + 2] = eg * dq2 + beta * (vr[r + 2] - eg * dk2) * kq;
            op[r + 3] = eg * dq3 + beta * (vr[r + 3] - eg * dk3) * kq;
        }

        c0 = n0; c1 = n1; c2 = n2; c3 = n3;
    }
}

extern "C" void kernel_launch(void* const* d_in, const int* in_sizes, int n_in,
                              void* d_out, int out_size)
{
    const float* mixed_qkv  = (const float*)d_in[0];
    const float* bgate      = (const float*)d_in[1];
    const float* agate      = (const float*)d_in[2];
    const float* conv_state = (const float*)d_in[3];
    const float* conv_w     = (const float*)d_in[4];
    const float* ssm        = (const float*)d_in[5];
    const float* alog       = (const float*)d_in[6];
    const float* dt_bias    = (const float*)d_in[7];
    float* out = (float*)d_out;

    const int B = in_sizes[0] / QKVD;
    gdn_prep_kernel<<<B * NKH, 128>>>(mixed_qkv, bgate, agate, conv_state,
                                      conv_w, alog, dt_bias);
    gdn_stream_kernel<<<B * NVH, 128>>>(ssm, out);
}

// round 7
// speedup vs baseline: 1.0691x; 1.0691x over previous
#include <cuda_runtime.h>
#include <math.h>

#define HKD  128
#define NKH  16
#define NVH  32
#define QKVD 8192

__device__ __forceinline__ float wredu(float v) {
#pragma unroll
    for (int o = 16; o; o >>= 1) v += __shfl_xor_sync(0xffffffffu, v, o);
    return v;
}

__device__ __forceinline__ float dot4(float4 a, float4 b) {
    return a.x * b.x + a.y * b.y + a.z * b.z + a.w * b.w;
}

// One CTA per (batch, k-head) pair. The CTA streams head 2hp's 128x128 state
// tile, then head 2hp+1's, sequentially: one prologue per 128 KB and zero
// load-gap between tiles (tile1 batch0 is prefetched by tile0's last batch).
__global__ __launch_bounds__(128) void gdn_decode_kernel(
    const float* __restrict__ mixed_qkv,
    const float* __restrict__ bgate,
    const float* __restrict__ agate,
    const float* __restrict__ conv_state,
    const float* __restrict__ conv_w,
    const float* __restrict__ ssm,
    const float* __restrict__ alog,
    const float* __restrict__ dt_bias,
    float* __restrict__ out)
{
    const int pair = blockIdx.x;
    const int b    = pair >> 4;
    const int hp   = pair & 15;
    const int t    = threadIdx.x;
    const int lane = t & 31;
    const int wid  = t >> 5;
    const int bh0  = b * NVH + hp * 2;

    __shared__ __align__(16) float q_s[HKD];
    __shared__ __align__(16) float k_s[HKD];
    __shared__ __align__(16) float v_s[2 * HKD];
    __shared__ float red[12];

    // ---- prefetch tile0 batch 0 BEFORE any prologue work ----
    const float4* Sb0 = (const float4*)(ssm + (size_t)bh0 * HKD * HKD)
                        + (size_t)wid * 32 * 32 + lane;
    const float4* Sb1 = Sb0 + HKD * 32;     // next head's tile is contiguous
    float4 c0 = __ldcs(Sb0 + 0 * 32);
    float4 c1 = __ldcs(Sb0 + 1 * 32);
    float4 c2 = __ldcs(Sb0 + 2 * 32);
    float4 c3 = __ldcs(Sb0 + 3 * 32);

    // ---- causal conv (4 taps) + SiLU: q, k, v0, v1 (4 channels/thread) ----
    const float* cs = conv_state + (size_t)b * 3 * QKVD;
    const float* mq = mixed_qkv  + (size_t)b * QKVD;
    const int cq  = hp * HKD + t;
    const int ck  = NKH * HKD + hp * HKD + t;
    const int cv0 = 2 * NKH * HKD + hp * 2 * HKD + t;
    const int cv1 = cv0 + HKD;

    float4 w = *(const float4*)(conv_w + (size_t)cq * 4);
    float x  = cs[cq] * w.x + cs[QKVD + cq] * w.y + cs[2 * QKVD + cq] * w.z + mq[cq] * w.w;
    const float qx = x / (1.f + expf(-x));

    w = *(const float4*)(conv_w + (size_t)ck * 4);
    x = cs[ck] * w.x + cs[QKVD + ck] * w.y + cs[2 * QKVD + ck] * w.z + mq[ck] * w.w;
    const float kx = x / (1.f + expf(-x));

    w = *(const float4*)(conv_w + (size_t)cv0 * 4);
    x = cs[cv0] * w.x + cs[QKVD + cv0] * w.y + cs[2 * QKVD + cv0] * w.z + mq[cv0] * w.w;
    v_s[t] = x / (1.f + expf(-x));

    w = *(const float4*)(conv_w + (size_t)cv1 * 4);
    x = cs[cv1] * w.x + cs[QKVD + cv1] * w.y + cs[2 * QKVD + cv1] * w.z + mq[cv1] * w.w;
    v_s[HKD + t] = x / (1.f + expf(-x));

    q_s[t] = qx;
    k_s[t] = kx;
    float pq = wredu(qx * qx);
    float pk = wredu(kx * kx);
    float pc = wredu(qx * kx);
    if (lane == 0) { red[wid] = pq; red[4 + wid] = pk; red[8 + wid] = pc; }

    // ---- per-head gating scalars (hide behind the barrier) ----
    const float a0 = agate[(size_t)bh0]     + dt_bias[hp * 2];
    const float a1 = agate[(size_t)bh0 + 1] + dt_bias[hp * 2 + 1];
    const float eg0 = expf(-expf(alog[hp * 2])     * (fmaxf(a0, 0.f) + log1pf(expf(-fabsf(a0)))));
    const float eg1 = expf(-expf(alog[hp * 2 + 1]) * (fmaxf(a1, 0.f) + log1pf(expf(-fabsf(a1)))));
    const float be0 = 1.f / (1.f + expf(-bgate[(size_t)bh0]));
    const float be1 = 1.f / (1.f + expf(-bgate[(size_t)bh0 + 1]));

    __syncthreads();   // the only barrier

    const float rq = rsqrtf(red[0] + red[1] + red[2] + red[3] + 1e-6f)
                     * 0.08838834764831845f;                        // * HK^-0.5
    const float rk = rsqrtf(red[4] + red[5] + red[6] + red[7] + 1e-6f);
    const float kq = (red[8] + red[9] + red[10] + red[11]) * rq * rk;

    float4 q4 = ((const float4*)q_s)[lane];
    q4.x *= rq; q4.y *= rq; q4.z *= rq; q4.w *= rq;
    float4 k4 = ((const float4*)k_s)[lane];
    k4.x *= rk; k4.y *= rk; k4.z *= rk; k4.w *= rk;

    // epilogue constants: o = eg*dq + bk*v - bke*dk
    const float bk0 = be0 * kq, bke0 = bk0 * eg0;
    const float bk1 = be1 * kq, bke1 = bk1 * eg1;

    float* op = out + (size_t)bh0 * HKD + wid * 32;

    // ---- tile 0: 8 batches; batch 7's "next" loads fetch tile1 batch 0 ----
#pragma unroll
    for (int j = 0; j < 8; j++) {
        const float4* nb = (j < 7) ? (Sb0 + (j + 1) * 4 * 32) : Sb1;
        float4 n0 = __ldcs(nb + 0 * 32);
        float4 n1 = __ldcs(nb + 1 * 32);
        float4 n2 = __ldcs(nb + 2 * 32);
        float4 n3 = __ldcs(nb + 3 * 32);

        float dk0 = dot4(c0, k4), dq0 = dot4(c0, q4);
        float dk1 = dot4(c1, k4), dq1 = dot4(c1, q4);
        float dk2 = dot4(c2, k4), dq2 = dot4(c2, q4);
        float dk3 = dot4(c3, k4), dq3 = dot4(c3, q4);

        dk0 = wredu(dk0); dq0 = wredu(dq0);
        dk1 = wredu(dk1); dq1 = wredu(dq1);
        dk2 = wredu(dk2); dq2 = wredu(dq2);
        dk3 = wredu(dk3); dq3 = wredu(dq3);

        if (lane == 0) {
            const int r = j * 4;
            const float* vr = v_s + wid * 32;
            op[r + 0] = fmaf(eg0, dq0, fmaf(bk0, vr[r + 0], -bke0 * dk0));
            op[r + 1] = fmaf(eg0, dq1, fmaf(bk0, vr[r + 1], -bke0 * dk1));
            op[r + 2] = fmaf(eg0, dq2, fmaf(bk0, vr[r + 2], -bke0 * dk2));
            op[r + 3] = fmaf(eg0, dq3, fmaf(bk0, vr[r + 3], -bke0 * dk3));
        }
        c0 = n0; c1 = n1; c2 = n2; c3 = n3;
    }

    op += HKD;   // head 2hp+1 output

    // ---- tile 1: 8 batches ----
#pragma unroll
    for (int j = 0; j < 8; j++) {
        float4 n0 = {}, n1 = {}, n2 = {}, n3 = {};
        if (j < 7) {
            n0 = __ldcs(Sb1 + ((j + 1) * 4 + 0) * 32);
            n1 = __ldcs(Sb1 + ((j + 1) * 4 + 1) * 32);
            n2 = __ldcs(Sb1 + ((j + 1) * 4 + 2) * 32);
            n3 = __ldcs(Sb1 + ((j + 1) * 4 + 3) * 32);
        }

        float dk0 = dot4(c0, k4), dq0 = dot4(c0, q4);
        float dk1 = dot4(c1, k4), dq1 = dot4(c1, q4);
        float dk2 = dot4(c2, k4), dq2 = dot4(c2, q4);
        float dk3 = dot4(c3, k4), dq3 = dot4(c3, q4);

        dk0 = wredu(dk0); dq0 = wredu(dq0);
        dk1 = wredu(dk1); dq1 = wredu(dq1);
        dk2 = wredu(dk2); dq2 = wredu(dq2);
        dk3 = wredu(dk3); dq3 = wredu(dq3);

        if (lane == 0) {
            const int r = j * 4;
            const float* vr = v_s + HKD + wid * 32;
            op[r + 0] = fmaf(eg1, dq0, fmaf(bk1, vr[r + 0], -bke1 * dk0));
            op[r + 1] = fmaf(eg1, dq1, fmaf(bk1, vr[r + 1], -bke1 * dk1));
            op[r + 2] = fmaf(eg1, dq2, fmaf(bk1, vr[r + 2], -bke1 * dk2));
            op[r + 3] = fmaf(eg1, dq3, fmaf(bk1, vr[r + 3], -bke1 * dk3));
        }
        c0 = n0; c1 = n1; c2 = n2; c3 = n3;
    }
}

extern "C" void kernel_launch(void* const* d_in, const int* in_sizes, int n_in,
                              void* d_out, int out_size)
{
    const float* mixed_qkv  = (const float*)d_in[0];
    const float* bgate      = (const float*)d_in[1];
    const float* agate      = (const float*)d_in[2];
    const float* conv_state = (const float*)d_in[3];
    const float* conv_w     = (const float*)d_in[4];
    const float* ssm        = (const float*)d_in[5];
    const float* alog       = (const float*)d_in[6];
    const float* dt_bias    = (const float*)d_in[7];
    float* out = (float*)d_out;

    const int B = in_sizes[0] / QKVD;
    gdn_decode_kernel<<<B * NKH, 128>>>(mixed_qkv, bgate, agate, conv_state,
                                        conv_w, ssm, alog, dt_bias, out);
}